// round 6
// baseline (speedup 1.0000x reference)
#include <cuda_runtime.h>

// Integrate-and-fire scan fused with per-timestep 64x512 transpose.
//   v += x[t]; if (v > 2.0f) { spike[t] = 1; v = 0; }  (membrane reset at t=100)
// R3: tile = 8(wc) x 32(h), 256 threads, 1 neuron/thread.
//  - Store side now LINE-contiguous: warp STG.128 = 4 x 512B segments
//    (4 L1 wavefronts vs 16 in R2 -- L1 was the top unit at 62%).
//  - Double-buffered smem -> ONE barrier per 4-timestep group (25 total).
//  - Padded smem [8][36]: conflict-free STS (banks 4*wc+h) and LDS.128.

namespace {
constexpr int kH     = 64;
constexpr int kWC    = 512;                    // W*C
constexpr int kChunk = 100;
constexpr int kNPB   = kH * kWC;               // 32768 neurons / batch
constexpr long long kBS = 200LL * kNPB;        // batch stride
constexpr int kGroup = 4;                      // timesteps per barrier
constexpr int kNG    = kChunk / kGroup;        // 25
constexpr int kHT    = 32;                     // h tile
constexpr int kWT    = 8;                      // wc tile
constexpr int kPad   = 36;                     // padded h extent
constexpr float kTh  = 2.0f;
}

__global__ void __launch_bounds__(256)
integrator_kernel(const float* __restrict__ in, float* __restrict__ out) {
    __shared__ float sm[2][kGroup][kWT][kPad];   // [buf][t][wc][h]

    const int tid = threadIdx.x;
    const int wcl = tid & 7;                     // 0..7
    const int hl  = tid >> 3;                    // 0..31
    const int wc0 = blockIdx.x * kWT;
    const int h0  = blockIdx.y * kHT;
    const int b   = blockIdx.z >> 1;
    const int t0  = (blockIdx.z & 1) * kChunk;

    // Load side: neuron (h0+hl, wc0+wcl); warp = 4 h-rows x 8 consecutive wc
    // -> full 32B sectors.
    const float* pin = in + b * kBS + (long long)t0 * kNPB
                          + (h0 + hl) * kWC + wc0 + wcl;

    // Store side: per t-slice 64 threads, each one float4 of h.
    // Warp covers wc 0..3 x h 0..31 -> 4 contiguous 128B-aligned 512B runs.
    const int g2  = tid >> 6;                    // 0..3 t-slice in group
    const int idx = tid & 63;
    const int swc = idx >> 3;                    // 0..7
    const int sh4 = (idx & 7) * 4;               // 0,4,...,28
    float* pout = out + b * kBS + (long long)t0 * kNPB
                      + (wc0 + swc) * 64 + h0 + sh4;

    float v = 0.f;

    float nxt[kGroup];
#pragma unroll
    for (int g = 0; g < kGroup; ++g)
        nxt[g] = pin[(long long)g * kNPB];

    for (int gi = 0; gi < kNG; ++gi) {
        const int p = gi & 1;

        float cur[kGroup];
#pragma unroll
        for (int g = 0; g < kGroup; ++g) cur[g] = nxt[g];

        // Prefetch next group's 4 independent loads; they drain behind the
        // barrier + store phase + next compute.
        if (gi + 1 < kNG) {
            const float* pn = pin + (long long)(gi + 1) * kGroup * kNPB;
#pragma unroll
            for (int g = 0; g < kGroup; ++g)
                nxt[g] = pn[(long long)g * kNPB];
        }

#pragma unroll
        for (int g = 0; g < kGroup; ++g) {
            v += cur[g];
            const bool fire = v > kTh;
            sm[p][g][wcl][hl] = fire ? 1.f : 0.f;   // banks (4*wcl+hl)%32: unique
            v = fire ? 0.f : v;
        }
        __syncthreads();   // single barrier: double buffer makes reuse safe

        float4 o = *reinterpret_cast<const float4*>(&sm[p][g2][swc][sh4]);
        *reinterpret_cast<float4*>(
            pout + (long long)(gi * kGroup + g2) * kNPB) = o;
    }
}

extern "C" void kernel_launch(void* const* d_in, const int* in_sizes, int n_in,
                              void* d_out, int out_size) {
    (void)in_sizes; (void)n_in; (void)out_size;
    const float* in = (const float*)d_in[0];
    float* out = (float*)d_out;
    dim3 grid(kWC / kWT, kH / kHT, 4 * 2);   // 64 x 2 x 8 = 1024 blocks
    integrator_kernel<<<grid, 256>>>(in, out);
}